// round 14
// baseline (speedup 1.0000x reference)
#include <cuda_runtime.h>
#include <cstdint>
#include <cstddef>

// Problem constants
#define NN 100000
#define EE 1600000
#define FF 128
#define LL 4
#define GG 512
#define OUTC 10
#define EPSV 1e-5f

// ---------------- device scratch (static, no runtime allocation) ----------------
__device__ float g_h[(size_t)NN * FF];     // current node features
__device__ float g_hw[(size_t)NN * FF];    // h @ W
__device__ float g_agg[(size_t)NN * FF];   // scatter destination
__device__ float g_deg[NN];
__device__ float g_dinv[NN];
__device__ float g_stats[2 * FF];          // per-channel sum, sumsq
__device__ float g_pooled[(size_t)GG * LL * FF];
__device__ float g_z1[(size_t)GG * FF];
__device__ float g_stats2[2 * FF];

// ---------------- setup kernels ----------------
__global__ void zero_setup_kernel() {
    size_t i = (size_t)blockIdx.x * blockDim.x + threadIdx.x;
    size_t stride = (size_t)gridDim.x * blockDim.x;
    for (size_t j = i; j < (size_t)GG * LL * FF; j += stride) g_pooled[j] = 0.f;
    for (size_t j = i; j < NN; j += stride) g_deg[j] = 0.f;
}

// degree of destination nodes (edge_index row 1 = col)
__global__ void setup_deg_kernel(const int* __restrict__ ei) {
    size_t i = (size_t)blockIdx.x * blockDim.x + threadIdx.x;
    size_t stride = (size_t)gridDim.x * blockDim.x;
    for (size_t e = i; e < EE; e += stride) {
        int c = ei[EE + e];
        atomicAdd(&g_deg[c], 1.0f);
    }
}

__global__ void compute_dinv_kernel() {
    size_t i = (size_t)blockIdx.x * blockDim.x + threadIdx.x;
    size_t stride = (size_t)gridDim.x * blockDim.x;
    for (size_t j = i; j < NN; j += stride) {
        float d = g_deg[j];
        g_dinv[j] = d > 0.f ? rsqrtf(d) : 0.f;
    }
}

// zero agg + stats for a layer
__global__ void zero_layer_kernel() {
    size_t i = (size_t)blockIdx.x * blockDim.x + threadIdx.x;
    size_t stride = (size_t)gridDim.x * blockDim.x;
    float4* p = (float4*)g_agg;
    size_t n4 = (size_t)NN * FF / 4;
    float4 z = make_float4(0.f, 0.f, 0.f, 0.f);
    for (size_t j = i; j < n4; j += stride) p[j] = z;
    if (i < 2 * FF) g_stats[i] = 0.f;
}

// ---------------- SGEMM: C[M,128] = A[M,128] @ W[128,128] ----------------
// BM=128, BN=128, BK=8, 256 threads, 8x8 register tile per thread
__global__ void __launch_bounds__(256) sgemm128_kernel(const float* __restrict__ x,
                                                       int use_x,
                                                       const float* __restrict__ W,
                                                       int M) {
    __shared__ float As[8][128];
    __shared__ float Bs[8][128];
    const float* __restrict__ A = use_x ? x : g_h;
    float* __restrict__ C = g_hw;

    const int tid = threadIdx.x;
    const int m0 = blockIdx.x * 128;
    const int tr = (tid >> 4) << 3;   // 0..120
    const int tc = (tid & 15) << 3;   // 0..120

    const int a_row = tid >> 1;         // 0..127
    const int a_col = (tid & 1) << 2;   // 0 or 4
    const int b_row = tid >> 5;         // 0..7
    const int b_col = (tid & 31) << 2;  // 0..124

    float acc[8][8];
#pragma unroll
    for (int i = 0; i < 8; i++)
#pragma unroll
        for (int j = 0; j < 8; j++) acc[i][j] = 0.f;

    for (int k0 = 0; k0 < 128; k0 += 8) {
        float4 av = make_float4(0.f, 0.f, 0.f, 0.f);
        int gr = m0 + a_row;
        if (gr < M) av = *(const float4*)(A + (size_t)gr * 128 + k0 + a_col);
        As[a_col + 0][a_row] = av.x;
        As[a_col + 1][a_row] = av.y;
        As[a_col + 2][a_row] = av.z;
        As[a_col + 3][a_row] = av.w;
        float4 bv = *(const float4*)(W + (size_t)(k0 + b_row) * 128 + b_col);
        *(float4*)&Bs[b_row][b_col] = bv;
        __syncthreads();
#pragma unroll
        for (int k = 0; k < 8; k++) {
            float ra[8], rb[8];
            *(float4*)&ra[0] = *(const float4*)&As[k][tr];
            *(float4*)&ra[4] = *(const float4*)&As[k][tr + 4];
            *(float4*)&rb[0] = *(const float4*)&Bs[k][tc];
            *(float4*)&rb[4] = *(const float4*)&Bs[k][tc + 4];
#pragma unroll
            for (int i = 0; i < 8; i++)
#pragma unroll
                for (int j = 0; j < 8; j++)
                    acc[i][j] = fmaf(ra[i], rb[j], acc[i][j]);
        }
        __syncthreads();
    }
#pragma unroll
    for (int i = 0; i < 8; i++) {
        int gr = m0 + tr + i;
        if (gr < M) {
            *(float4*)(C + (size_t)gr * 128 + tc) =
                make_float4(acc[i][0], acc[i][1], acc[i][2], acc[i][3]);
            *(float4*)(C + (size_t)gr * 128 + tc + 4) =
                make_float4(acc[i][4], acc[i][5], acc[i][6], acc[i][7]);
        }
    }
}

// ---------------- edge scatter: agg[col] += dinv[row]*dinv[col] * hw[row] ----
// warp per edge, lane handles 4 contiguous channels, vector RED
__global__ void __launch_bounds__(256) scatter_kernel(const int* __restrict__ ei) {
    size_t warp = ((size_t)blockIdx.x * blockDim.x + threadIdx.x) >> 5;
    int lane = threadIdx.x & 31;
    if (warp >= EE) return;
    int r = ei[warp];
    int c = ei[EE + warp];
    float nm = g_dinv[r] * g_dinv[c];
    float4 v = *((const float4*)(g_hw + (size_t)r * 128) + lane);
    float ox = v.x * nm, oy = v.y * nm, oz = v.z * nm, ow = v.w * nm;
    float* dst = g_agg + (size_t)c * 128 + lane * 4;
    asm volatile("red.global.add.v4.f32 [%0], {%1,%2,%3,%4};"
                 :: "l"(dst), "f"(ox), "f"(oy), "f"(oz), "f"(ow)
                 : "memory");
}

// ---------------- per-channel BN stats of relu(agg + b) ----------------
__global__ void __launch_bounds__(256) stats_kernel(const float* __restrict__ bias) {
    int c = threadIdx.x & 127;
    int sub = threadIdx.x >> 7;  // 0/1
    float b = bias[c];
    float s = 0.f, s2 = 0.f;
    for (int r = blockIdx.x * 2 + sub; r < NN; r += gridDim.x * 2) {
        float v = g_agg[(size_t)r * 128 + c] + b;
        v = fmaxf(v, 0.f);
        s += v;
        s2 = fmaf(v, v, s2);
    }
    __shared__ float sh[2][256];
    sh[0][threadIdx.x] = s;
    sh[1][threadIdx.x] = s2;
    __syncthreads();
    if (sub == 0) {
        atomicAdd(&g_stats[c], sh[0][c] + sh[0][c + 128]);
        atomicAdd(&g_stats[128 + c], sh[1][c] + sh[1][c + 128]);
    }
}

// ---------------- normalize + write h + pooled segment sum ----------------
__global__ void __launch_bounds__(256) norm_pool_kernel(int layer,
                                                        const int* __restrict__ batch,
                                                        const float* __restrict__ bias,
                                                        const float* __restrict__ gamma,
                                                        const float* __restrict__ beta) {
    int c = threadIdx.x & 127;
    int sub = threadIdx.x >> 7;
    int chunk = (NN + gridDim.x - 1) / gridDim.x;
    int r0 = blockIdx.x * chunk;
    int r1 = min(r0 + chunk, NN);

    const float invN = 1.0f / (float)NN;
    float mu = g_stats[c] * invN;
    float var = g_stats[128 + c] * invN - mu * mu;
    float sc = rsqrtf(var + EPSV) * gamma[c];
    float sh = beta[c] - mu * sc;
    float b = bias[c];

    int curg = -1;
    float acc = 0.f;
    for (int r = r0 + sub; r < r1; r += 2) {
        float v = fmaxf(g_agg[(size_t)r * 128 + c] + b, 0.f) * sc + sh;
        g_h[(size_t)r * 128 + c] = v;
        int g = batch[r];
        if (g != curg) {
            if (curg >= 0)
                atomicAdd(&g_pooled[(size_t)curg * (LL * FF) + layer * FF + c], acc);
            curg = g;
            acc = 0.f;
        }
        acc += v;
    }
    if (curg >= 0)
        atomicAdd(&g_pooled[(size_t)curg * (LL * FF) + layer * FF + c], acc);
}

// ---------------- MLP head ----------------
// z1[g,c] = sum_k pooled[g,k] * W1[k,c] + b1[c]
__global__ void __launch_bounds__(128) mlp1_kernel(const float* __restrict__ W1,
                                                   const float* __restrict__ b1) {
    int g = blockIdx.x;
    int c = threadIdx.x;
    const float* p = g_pooled + (size_t)g * (LL * FF);
    float a0 = 0.f, a1 = 0.f, a2 = 0.f, a3 = 0.f;
#pragma unroll 4
    for (int k = 0; k < LL * FF; k += 4) {
        a0 = fmaf(p[k + 0], W1[(size_t)(k + 0) * FF + c], a0);
        a1 = fmaf(p[k + 1], W1[(size_t)(k + 1) * FF + c], a1);
        a2 = fmaf(p[k + 2], W1[(size_t)(k + 2) * FF + c], a2);
        a3 = fmaf(p[k + 3], W1[(size_t)(k + 3) * FF + c], a3);
    }
    g_z1[(size_t)g * FF + c] = (a0 + a1) + (a2 + a3) + b1[c];
}

__global__ void __launch_bounds__(128) bn2_stats_kernel() {
    int c = threadIdx.x;
    float s = 0.f, s2 = 0.f;
    for (int g = 0; g < GG; g++) {
        float v = g_z1[(size_t)g * FF + c];
        s += v;
        s2 = fmaf(v, v, s2);
    }
    g_stats2[c] = s;
    g_stats2[128 + c] = s2;
}

__global__ void __launch_bounds__(128) mlp2_kernel(const float* __restrict__ g1,
                                                   const float* __restrict__ bt1,
                                                   const float* __restrict__ W2,
                                                   const float* __restrict__ b2,
                                                   float* __restrict__ out) {
    int g = blockIdx.x;
    int c = threadIdx.x;
    __shared__ float y[FF];
    const float invG = 1.0f / (float)GG;
    float mu = g_stats2[c] * invG;
    float var = g_stats2[128 + c] * invG - mu * mu;
    float v = (g_z1[(size_t)g * FF + c] - mu) * rsqrtf(var + EPSV) * g1[c] + bt1[c];
    y[c] = fmaxf(v, 0.f);
    __syncthreads();
    if (c < OUTC) {
        float acc = b2[c];
#pragma unroll 8
        for (int k = 0; k < FF; k++)
            acc = fmaf(y[k], W2[(size_t)k * OUTC + c], acc);
        out[(size_t)g * OUTC + c] = acc;
    }
}

// ---------------- launch ----------------
extern "C" void kernel_launch(void* const* d_in, const int* in_sizes, int n_in,
                              void* d_out, int out_size) {
    const float* x = (const float*)d_in[0];
    const int* ei = (const int*)d_in[1];       // int32: JAX x64 disabled -> int32
    const int* batch = (const int*)d_in[2];    // int32
    const float* Ws = (const float*)d_in[3];
    const float* bs = (const float*)d_in[4];
    const float* gammas = (const float*)d_in[5];
    const float* betas = (const float*)d_in[6];
    const float* W1 = (const float*)d_in[7];
    const float* b1 = (const float*)d_in[8];
    const float* g1 = (const float*)d_in[9];
    const float* bt1 = (const float*)d_in[10];
    const float* W2 = (const float*)d_in[11];
    const float* b2 = (const float*)d_in[12];
    float* out = (float*)d_out;

    zero_setup_kernel<<<512, 256>>>();
    setup_deg_kernel<<<2048, 256>>>(ei);
    compute_dinv_kernel<<<512, 256>>>();

    const int gemm_blocks = (NN + 127) / 128;        // 782
    const int scatter_blocks = (EE * 32) / 256;      // 200000

    for (int t = 0; t < LL; t++) {
        zero_layer_kernel<<<2048, 256>>>();
        sgemm128_kernel<<<gemm_blocks, 256>>>(x, t == 0 ? 1 : 0,
                                              Ws + (size_t)t * FF * FF, NN);
        scatter_kernel<<<scatter_blocks, 256>>>(ei);
        stats_kernel<<<2048, 256>>>(bs + (size_t)t * FF);
        norm_pool_kernel<<<1024, 256>>>(t, batch, bs + (size_t)t * FF,
                                        gammas + (size_t)t * FF,
                                        betas + (size_t)t * FF);
    }

    mlp1_kernel<<<GG, 128>>>(W1, b1);
    bn2_stats_kernel<<<1, 128>>>();
    mlp2_kernel<<<GG, 128>>>(g1, bt1, W2, b2, out);
}

// round 15
// speedup vs baseline: 1.0720x; 1.0720x over previous
#include <cuda_runtime.h>
#include <cstdint>
#include <cstddef>

// Problem constants
#define NN 100000
#define EE 1600000
#define FF 128
#define LL 4
#define GG 512
#define OUTC 10
#define EPSV 1e-5f

// ---------------- device scratch (static, no runtime allocation) ----------------
__device__ float g_hw[(size_t)NN * FF];    // h @ W
__device__ float g_agg[(size_t)NN * FF];   // relu(aggregate + bias), pre-affine
__device__ float g_dinv[NN];
__device__ int   g_cnt[NN];                // per-node in-degree (histogram)
__device__ int   g_rowptr[NN + 1];         // CSR offsets (by destination col)
__device__ int   g_off[NN];                // placement cursors
__device__ int   g_erow[EE];               // CSR-ordered source (row) ids
__device__ float g_stats[LL * 2 * FF];     // per-layer per-channel sum, sumsq
__device__ float g_sc[LL * FF];            // BN scale per layer
__device__ float g_sh[LL * FF];            // BN shift per layer
__device__ float g_praw[(size_t)GG * LL * FF]; // per-graph sums of raw relu values
__device__ float g_gcnt[GG];               // nodes per graph
__device__ float g_z1[(size_t)GG * FF];
__device__ float g_stats2[2 * FF];

// ---------------- setup kernels ----------------
__global__ void zero_setup_kernel() {
    size_t i = (size_t)blockIdx.x * blockDim.x + threadIdx.x;
    size_t stride = (size_t)gridDim.x * blockDim.x;
    for (size_t j = i; j < (size_t)GG * LL * FF; j += stride) g_praw[j] = 0.f;
    for (size_t j = i; j < NN; j += stride) g_cnt[j] = 0;
    for (size_t j = i; j < LL * 2 * FF; j += stride) g_stats[j] = 0.f;
    for (size_t j = i; j < GG; j += stride) g_gcnt[j] = 0.f;
}

__global__ void hist_kernel(const int* __restrict__ ei) {
    size_t i = (size_t)blockIdx.x * blockDim.x + threadIdx.x;
    size_t stride = (size_t)gridDim.x * blockDim.x;
    for (size_t e = i; e < EE; e += stride)
        atomicAdd(&g_cnt[ei[EE + e]], 1);
}

__global__ void gcnt_kernel(const int* __restrict__ batch) {
    size_t i = (size_t)blockIdx.x * blockDim.x + threadIdx.x;
    size_t stride = (size_t)gridDim.x * blockDim.x;
    for (size_t j = i; j < NN; j += stride)
        atomicAdd(&g_gcnt[batch[j]], 1.0f);
}

// single-block exclusive scan of g_cnt -> g_rowptr / g_off, plus dinv
__global__ void __launch_bounds__(1024) scan_kernel() {
    __shared__ int sh[1024];
    int t = threadIdx.x;
    const int chunk = (NN + 1023) / 1024;
    int lo = t * chunk;
    int hi = lo + chunk; if (hi > NN) hi = NN;
    int s = 0;
    for (int i = lo; i < hi; i++) s += g_cnt[i];
    sh[t] = s;
    __syncthreads();
    for (int d = 1; d < 1024; d <<= 1) {
        int v = (t >= d) ? sh[t - d] : 0;
        __syncthreads();
        sh[t] += v;
        __syncthreads();
    }
    int run = (t == 0) ? 0 : sh[t - 1];
    for (int i = lo; i < hi; i++) {
        g_rowptr[i] = run;
        g_off[i] = run;
        int c = g_cnt[i];
        g_dinv[i] = c > 0 ? rsqrtf((float)c) : 0.f;
        run += c;
    }
    if (t == 1023) g_rowptr[NN] = run;
}

__global__ void place_kernel(const int* __restrict__ ei) {
    size_t i = (size_t)blockIdx.x * blockDim.x + threadIdx.x;
    size_t stride = (size_t)gridDim.x * blockDim.x;
    for (size_t e = i; e < EE; e += stride) {
        int r = ei[e];
        int c = ei[EE + e];
        int pos = atomicAdd(&g_off[c], 1);
        g_erow[pos] = r;
    }
}

// ---------------- SGEMM: C[M,128] = affine(A)[M,128] @ W[128,128] ------------
// layer_affine < 0: A = x (external), no affine.
// layer_affine >= 0: A = g_agg, element (row,k) -> a*g_sc[la*128+k]+g_sh[la*128+k]
__global__ void __launch_bounds__(256) sgemm128_kernel(const float* __restrict__ x,
                                                       const float* __restrict__ W,
                                                       int layer_affine,
                                                       int M) {
    __shared__ float As[8][128];
    __shared__ float Bs[8][128];
    const float* __restrict__ A = (layer_affine < 0) ? x : g_agg;
    float* __restrict__ C = g_hw;

    const int tid = threadIdx.x;
    const int m0 = blockIdx.x * 128;
    const int tr = (tid >> 4) << 3;
    const int tc = (tid & 15) << 3;

    const int a_row = tid >> 1;
    const int a_col = (tid & 1) << 2;
    const int b_row = tid >> 5;
    const int b_col = (tid & 31) << 2;

    float acc[8][8];
#pragma unroll
    for (int i = 0; i < 8; i++)
#pragma unroll
        for (int j = 0; j < 8; j++) acc[i][j] = 0.f;

    for (int k0 = 0; k0 < 128; k0 += 8) {
        float4 av = make_float4(0.f, 0.f, 0.f, 0.f);
        int gr = m0 + a_row;
        if (gr < M) {
            av = *(const float4*)(A + (size_t)gr * 128 + k0 + a_col);
            if (layer_affine >= 0) {
                const float* scp = g_sc + layer_affine * FF + k0 + a_col;
                const float* shp = g_sh + layer_affine * FF + k0 + a_col;
                float4 s4 = *(const float4*)scp;
                float4 h4 = *(const float4*)shp;
                av.x = fmaf(av.x, s4.x, h4.x);
                av.y = fmaf(av.y, s4.y, h4.y);
                av.z = fmaf(av.z, s4.z, h4.z);
                av.w = fmaf(av.w, s4.w, h4.w);
            }
        }
        As[a_col + 0][a_row] = av.x;
        As[a_col + 1][a_row] = av.y;
        As[a_col + 2][a_row] = av.z;
        As[a_col + 3][a_row] = av.w;
        float4 bv = *(const float4*)(W + (size_t)(k0 + b_row) * 128 + b_col);
        *(float4*)&Bs[b_row][b_col] = bv;
        __syncthreads();
#pragma unroll
        for (int k = 0; k < 8; k++) {
            float ra[8], rb[8];
            *(float4*)&ra[0] = *(const float4*)&As[k][tr];
            *(float4*)&ra[4] = *(const float4*)&As[k][tr + 4];
            *(float4*)&rb[0] = *(const float4*)&Bs[k][tc];
            *(float4*)&rb[4] = *(const float4*)&Bs[k][tc + 4];
#pragma unroll
            for (int i = 0; i < 8; i++)
#pragma unroll
                for (int j = 0; j < 8; j++)
                    acc[i][j] = fmaf(ra[i], rb[j], acc[i][j]);
        }
        __syncthreads();
    }
#pragma unroll
    for (int i = 0; i < 8; i++) {
        int gr = m0 + tr + i;
        if (gr < M) {
            *(float4*)(C + (size_t)gr * 128 + tc) =
                make_float4(acc[i][0], acc[i][1], acc[i][2], acc[i][3]);
            *(float4*)(C + (size_t)gr * 128 + tc + 4) =
                make_float4(acc[i][4], acc[i][5], acc[i][6], acc[i][7]);
        }
    }
}

// ---------------- fused aggregation: CSR gather + bias + relu + BN stats ----
__global__ void __launch_bounds__(256) aggregate_kernel(int layer,
                                                        const float* __restrict__ bias) {
    const int warp = threadIdx.x >> 5;
    const int lane = threadIdx.x & 31;
    const int node = blockIdx.x * 8 + warp;

    float4 acc = make_float4(0.f, 0.f, 0.f, 0.f);
    if (node < NN) {
        int p = g_rowptr[node];
        const int end = g_rowptr[node + 1];
        const float dc = g_dinv[node];
        for (; p + 2 <= end; p += 2) {
            int r0 = g_erow[p];
            int r1 = g_erow[p + 1];
            float w0 = g_dinv[r0];
            float w1 = g_dinv[r1];
            float4 v0 = *((const float4*)(g_hw + (size_t)r0 * 128) + lane);
            float4 v1 = *((const float4*)(g_hw + (size_t)r1 * 128) + lane);
            acc.x += w0 * v0.x + w1 * v1.x;
            acc.y += w0 * v0.y + w1 * v1.y;
            acc.z += w0 * v0.z + w1 * v1.z;
            acc.w += w0 * v0.w + w1 * v1.w;
        }
        if (p < end) {
            int r0 = g_erow[p];
            float w0 = g_dinv[r0];
            float4 v0 = *((const float4*)(g_hw + (size_t)r0 * 128) + lane);
            acc.x += w0 * v0.x;
            acc.y += w0 * v0.y;
            acc.z += w0 * v0.z;
            acc.w += w0 * v0.w;
        }
        float4 b4 = *((const float4*)bias + lane);
        acc.x = fmaxf(fmaf(acc.x, dc, b4.x), 0.f);
        acc.y = fmaxf(fmaf(acc.y, dc, b4.y), 0.f);
        acc.z = fmaxf(fmaf(acc.z, dc, b4.z), 0.f);
        acc.w = fmaxf(fmaf(acc.w, dc, b4.w), 0.f);
        *((float4*)(g_agg + (size_t)node * 128) + lane) = acc;
    }

    __shared__ float ssum[8][128];
    __shared__ float ssq[8][128];
    int c0 = lane * 4;
    ssum[warp][c0 + 0] = acc.x;  ssq[warp][c0 + 0] = acc.x * acc.x;
    ssum[warp][c0 + 1] = acc.y;  ssq[warp][c0 + 1] = acc.y * acc.y;
    ssum[warp][c0 + 2] = acc.z;  ssq[warp][c0 + 2] = acc.z * acc.z;
    ssum[warp][c0 + 3] = acc.w;  ssq[warp][c0 + 3] = acc.w * acc.w;
    __syncthreads();
    int c = threadIdx.x & 127;
    bool issq = threadIdx.x >= 128;
    float t = 0.f;
#pragma unroll
    for (int i = 0; i < 8; i++) t += issq ? ssq[i][c] : ssum[i][c];
    atomicAdd(&g_stats[layer * 256 + (issq ? 128 : 0) + c], t);
}

// ---------------- BN params ----------------
__global__ void __launch_bounds__(128) bnparams_kernel(int layer,
                                                       const float* __restrict__ gamma,
                                                       const float* __restrict__ beta) {
    int c = threadIdx.x;
    const float invN = 1.0f / (float)NN;
    float mu = g_stats[layer * 256 + c] * invN;
    float var = g_stats[layer * 256 + 128 + c] * invN - mu * mu;
    float sc = rsqrtf(var + EPSV) * gamma[c];
    g_sc[layer * FF + c] = sc;
    g_sh[layer * FF + c] = beta[c] - mu * sc;
}

// ---------------- pooled raw sums ----------------
__global__ void __launch_bounds__(256) pooled_raw_kernel(int layer,
                                                         const int* __restrict__ batch) {
    int c = threadIdx.x & 127;
    int sub = threadIdx.x >> 7;
    int chunk = (NN + gridDim.x - 1) / gridDim.x;
    int r0 = blockIdx.x * chunk;
    int r1 = min(r0 + chunk, NN);

    int curg = -1;
    float acc = 0.f;
    for (int r = r0 + sub; r < r1; r += 2) {
        float v = g_agg[(size_t)r * 128 + c];
        int g = batch[r];
        if (g != curg) {
            if (curg >= 0)
                atomicAdd(&g_praw[(size_t)curg * (LL * FF) + layer * FF + c], acc);
            curg = g;
            acc = 0.f;
        }
        acc += v;
    }
    if (curg >= 0)
        atomicAdd(&g_praw[(size_t)curg * (LL * FF) + layer * FF + c], acc);
}

// ---------------- MLP head ----------------
__global__ void __launch_bounds__(128) mlp1_kernel(const float* __restrict__ W1,
                                                   const float* __restrict__ b1) {
    int g = blockIdx.x;
    int c = threadIdx.x;
    const float* p = g_praw + (size_t)g * (LL * FF);
    const float cnt = g_gcnt[g];
    float a0 = 0.f, a1 = 0.f, a2 = 0.f, a3 = 0.f;
#pragma unroll 4
    for (int k = 0; k < LL * FF; k += 4) {
        float v0 = fmaf(g_sc[k + 0], p[k + 0], cnt * g_sh[k + 0]);
        float v1 = fmaf(g_sc[k + 1], p[k + 1], cnt * g_sh[k + 1]);
        float v2 = fmaf(g_sc[k + 2], p[k + 2], cnt * g_sh[k + 2]);
        float v3 = fmaf(g_sc[k + 3], p[k + 3], cnt * g_sh[k + 3]);
        a0 = fmaf(v0, W1[(size_t)(k + 0) * FF + c], a0);
        a1 = fmaf(v1, W1[(size_t)(k + 1) * FF + c], a1);
        a2 = fmaf(v2, W1[(size_t)(k + 2) * FF + c], a2);
        a3 = fmaf(v3, W1[(size_t)(k + 3) * FF + c], a3);
    }
    g_z1[(size_t)g * FF + c] = (a0 + a1) + (a2 + a3) + b1[c];
}

__global__ void __launch_bounds__(128) bn2_stats_kernel() {
    int c = threadIdx.x;
    float s = 0.f, s2 = 0.f;
    for (int g = 0; g < GG; g++) {
        float v = g_z1[(size_t)g * FF + c];
        s += v;
        s2 = fmaf(v, v, s2);
    }
    g_stats2[c] = s;
    g_stats2[128 + c] = s2;
}

__global__ void __launch_bounds__(128) mlp2_kernel(const float* __restrict__ g1,
                                                   const float* __restrict__ bt1,
                                                   const float* __restrict__ W2,
                                                   const float* __restrict__ b2,
                                                   float* __restrict__ out) {
    int g = blockIdx.x;
    int c = threadIdx.x;
    __shared__ float y[FF];
    const float invG = 1.0f / (float)GG;
    float mu = g_stats2[c] * invG;
    float var = g_stats2[128 + c] * invG - mu * mu;
    float v = (g_z1[(size_t)g * FF + c] - mu) * rsqrtf(var + EPSV) * g1[c] + bt1[c];
    y[c] = fmaxf(v, 0.f);
    __syncthreads();
    if (c < OUTC) {
        float acc = b2[c];
#pragma unroll 8
        for (int k = 0; k < FF; k++)
            acc = fmaf(y[k], W2[(size_t)k * OUTC + c], acc);
        out[(size_t)g * OUTC + c] = acc;
    }
}

// ---------------- launch ----------------
extern "C" void kernel_launch(void* const* d_in, const int* in_sizes, int n_in,
                              void* d_out, int out_size) {
    const float* x = (const float*)d_in[0];
    const int* ei = (const int*)d_in[1];
    const int* batch = (const int*)d_in[2];
    const float* Ws = (const float*)d_in[3];
    const float* bs = (const float*)d_in[4];
    const float* gammas = (const float*)d_in[5];
    const float* betas = (const float*)d_in[6];
    const float* W1 = (const float*)d_in[7];
    const float* b1 = (const float*)d_in[8];
    const float* g1 = (const float*)d_in[9];
    const float* bt1 = (const float*)d_in[10];
    const float* W2 = (const float*)d_in[11];
    const float* b2 = (const float*)d_in[12];
    float* out = (float*)d_out;

    zero_setup_kernel<<<512, 256>>>();
    hist_kernel<<<2048, 256>>>(ei);
    gcnt_kernel<<<512, 256>>>(batch);
    scan_kernel<<<1, 1024>>>();
    place_kernel<<<2048, 256>>>(ei);

    const int gemm_blocks = (NN + 127) / 128;   // 782
    const int agg_blocks = (NN + 7) / 8;        // 12500

    for (int t = 0; t < LL; t++) {
        sgemm128_kernel<<<gemm_blocks, 256>>>(x, Ws + (size_t)t * FF * FF,
                                              t - 1 /* -1 for t=0 -> use x */, NN);
        aggregate_kernel<<<agg_blocks, 256>>>(t, bs + (size_t)t * FF);
        bnparams_kernel<<<1, 128>>>(t, gammas + (size_t)t * FF, betas + (size_t)t * FF);
        pooled_raw_kernel<<<1024, 256>>>(t, batch);
    }

    mlp1_kernel<<<GG, 128>>>(W1, b1);
    bn2_stats_kernel<<<1, 128>>>();
    mlp2_kernel<<<GG, 128>>>(g1, bt1, W2, b2, out);
}

// round 16
// speedup vs baseline: 1.2649x; 1.1800x over previous
#include <cuda_runtime.h>
#include <cstdint>
#include <cstddef>

// Problem constants
#define NN 100000
#define EE 1600000
#define FF 128
#define LL 4
#define GG 512
#define OUTC 10
#define EPSV 1e-5f

#define SCAN_BS 512
#define SCAN_NB ((NN + SCAN_BS - 1) / SCAN_BS)   // 196

// ---------------- device scratch (static, no runtime allocation) ----------------
__device__ float g_hw[(size_t)NN * FF];    // h @ W
__device__ float g_agg[(size_t)NN * FF];   // relu(aggregate + bias), pre-affine
__device__ float g_dinv[NN];
__device__ int   g_cnt[NN];                // per-node in-degree (histogram)
__device__ int   g_rowptr[NN + 1];         // CSR offsets (by destination col)
__device__ int   g_off[NN];                // placement cursors
__device__ int   g_erow[EE];               // CSR-ordered source (row) ids
__device__ int   g_bsum[SCAN_NB];          // per-block count sums
__device__ int   g_boff[SCAN_NB];          // exclusive block offsets
__device__ float g_stats[LL * 2 * FF];     // per-layer per-channel sum, sumsq
__device__ float g_sc[LL * FF];            // BN scale per layer
__device__ float g_sh[LL * FF];            // BN shift per layer
__device__ float g_praw[(size_t)GG * LL * FF]; // per-graph sums of raw relu values
__device__ float g_gcnt[GG];               // nodes per graph
__device__ float g_z1[(size_t)GG * FF];
__device__ float g_stats2[2 * FF];

// ---------------- setup kernels ----------------
__global__ void zero_setup_kernel() {
    size_t i = (size_t)blockIdx.x * blockDim.x + threadIdx.x;
    size_t stride = (size_t)gridDim.x * blockDim.x;
    for (size_t j = i; j < (size_t)GG * LL * FF; j += stride) g_praw[j] = 0.f;
    for (size_t j = i; j < NN; j += stride) g_cnt[j] = 0;
    for (size_t j = i; j < LL * 2 * FF; j += stride) g_stats[j] = 0.f;
    for (size_t j = i; j < GG; j += stride) g_gcnt[j] = 0.f;
}

__global__ void hist_kernel(const int* __restrict__ ei) {
    size_t i = (size_t)blockIdx.x * blockDim.x + threadIdx.x;
    size_t stride = (size_t)gridDim.x * blockDim.x;
    for (size_t e = i; e < EE; e += stride)
        atomicAdd(&g_cnt[ei[EE + e]], 1);
}

__global__ void gcnt_kernel(const int* __restrict__ batch) {
    size_t i = (size_t)blockIdx.x * blockDim.x + threadIdx.x;
    size_t stride = (size_t)gridDim.x * blockDim.x;
    for (size_t j = i; j < NN; j += stride)
        atomicAdd(&g_gcnt[batch[j]], 1.0f);
}

// ---------------- parallel 3-phase scan of g_cnt ----------------
// Phase A: per-block sum of 512 counts
__global__ void __launch_bounds__(SCAN_BS) scanA_kernel() {
    __shared__ int sh[SCAN_BS];
    int t = threadIdx.x;
    int idx = blockIdx.x * SCAN_BS + t;
    sh[t] = (idx < NN) ? g_cnt[idx] : 0;
    __syncthreads();
#pragma unroll
    for (int d = SCAN_BS / 2; d > 0; d >>= 1) {
        if (t < d) sh[t] += sh[t + d];
        __syncthreads();
    }
    if (t == 0) g_bsum[blockIdx.x] = sh[0];
}

// Phase B: exclusive scan of the 196 block sums (one block)
__global__ void __launch_bounds__(256) scanB_kernel() {
    __shared__ int sh[256];
    int t = threadIdx.x;
    sh[t] = (t < SCAN_NB) ? g_bsum[t] : 0;
    __syncthreads();
    for (int d = 1; d < 256; d <<= 1) {
        int v = (t >= d) ? sh[t - d] : 0;
        __syncthreads();
        sh[t] += v;
        __syncthreads();
    }
    if (t < SCAN_NB) g_boff[t] = (t == 0) ? 0 : sh[t - 1];
}

// Phase C: per-block exclusive scan + block offset -> rowptr/off/dinv
__global__ void __launch_bounds__(SCAN_BS) scanC_kernel() {
    __shared__ int sh[SCAN_BS];
    int t = threadIdx.x;
    int idx = blockIdx.x * SCAN_BS + t;
    int c = (idx < NN) ? g_cnt[idx] : 0;
    sh[t] = c;
    __syncthreads();
    // Hillis-Steele inclusive scan over 512
    for (int d = 1; d < SCAN_BS; d <<= 1) {
        int v = (t >= d) ? sh[t - d] : 0;
        __syncthreads();
        sh[t] += v;
        __syncthreads();
    }
    if (idx < NN) {
        int excl = sh[t] - c + g_boff[blockIdx.x];
        g_rowptr[idx] = excl;
        g_off[idx] = excl;
        g_dinv[idx] = c > 0 ? rsqrtf((float)c) : 0.f;
    }
    if (idx == 0) g_rowptr[NN] = EE;  // all edge dests are in [0, NN)
}

__global__ void place_kernel(const int* __restrict__ ei) {
    size_t i = (size_t)blockIdx.x * blockDim.x + threadIdx.x;
    size_t stride = (size_t)gridDim.x * blockDim.x;
    for (size_t e = i; e < EE; e += stride) {
        int r = ei[e];
        int c = ei[EE + e];
        int pos = atomicAdd(&g_off[c], 1);
        g_erow[pos] = r;
    }
}

// ---------------- SGEMM: C[M,128] = affine(A)[M,128] @ W[128,128] ------------
// layer_affine < 0: A = x (external), no affine.
// layer_affine >= 0: A = g_agg, element (row,k) -> a*g_sc[la*128+k]+g_sh[la*128+k]
__global__ void __launch_bounds__(256) sgemm128_kernel(const float* __restrict__ x,
                                                       const float* __restrict__ W,
                                                       int layer_affine,
                                                       int M) {
    __shared__ float As[8][128];
    __shared__ float Bs[8][128];
    const float* __restrict__ A = (layer_affine < 0) ? x : g_agg;
    float* __restrict__ C = g_hw;

    const int tid = threadIdx.x;
    const int m0 = blockIdx.x * 128;
    const int tr = (tid >> 4) << 3;
    const int tc = (tid & 15) << 3;

    const int a_row = tid >> 1;
    const int a_col = (tid & 1) << 2;
    const int b_row = tid >> 5;
    const int b_col = (tid & 31) << 2;

    float acc[8][8];
#pragma unroll
    for (int i = 0; i < 8; i++)
#pragma unroll
        for (int j = 0; j < 8; j++) acc[i][j] = 0.f;

    for (int k0 = 0; k0 < 128; k0 += 8) {
        float4 av = make_float4(0.f, 0.f, 0.f, 0.f);
        int gr = m0 + a_row;
        if (gr < M) {
            av = *(const float4*)(A + (size_t)gr * 128 + k0 + a_col);
            if (layer_affine >= 0) {
                const float* scp = g_sc + layer_affine * FF + k0 + a_col;
                const float* shp = g_sh + layer_affine * FF + k0 + a_col;
                float4 s4 = *(const float4*)scp;
                float4 h4 = *(const float4*)shp;
                av.x = fmaf(av.x, s4.x, h4.x);
                av.y = fmaf(av.y, s4.y, h4.y);
                av.z = fmaf(av.z, s4.z, h4.z);
                av.w = fmaf(av.w, s4.w, h4.w);
            }
        }
        As[a_col + 0][a_row] = av.x;
        As[a_col + 1][a_row] = av.y;
        As[a_col + 2][a_row] = av.z;
        As[a_col + 3][a_row] = av.w;
        float4 bv = *(const float4*)(W + (size_t)(k0 + b_row) * 128 + b_col);
        *(float4*)&Bs[b_row][b_col] = bv;
        __syncthreads();
#pragma unroll
        for (int k = 0; k < 8; k++) {
            float ra[8], rb[8];
            *(float4*)&ra[0] = *(const float4*)&As[k][tr];
            *(float4*)&ra[4] = *(const float4*)&As[k][tr + 4];
            *(float4*)&rb[0] = *(const float4*)&Bs[k][tc];
            *(float4*)&rb[4] = *(const float4*)&Bs[k][tc + 4];
#pragma unroll
            for (int i = 0; i < 8; i++)
#pragma unroll
                for (int j = 0; j < 8; j++)
                    acc[i][j] = fmaf(ra[i], rb[j], acc[i][j]);
        }
        __syncthreads();
    }
#pragma unroll
    for (int i = 0; i < 8; i++) {
        int gr = m0 + tr + i;
        if (gr < M) {
            *(float4*)(C + (size_t)gr * 128 + tc) =
                make_float4(acc[i][0], acc[i][1], acc[i][2], acc[i][3]);
            *(float4*)(C + (size_t)gr * 128 + tc + 4) =
                make_float4(acc[i][4], acc[i][5], acc[i][6], acc[i][7]);
        }
    }
}

// ---------------- fused aggregation: CSR gather + bias + relu + BN stats ----
__global__ void __launch_bounds__(256) aggregate_kernel(int layer,
                                                        const float* __restrict__ bias) {
    const int warp = threadIdx.x >> 5;
    const int lane = threadIdx.x & 31;
    const int node = blockIdx.x * 8 + warp;

    float4 acc = make_float4(0.f, 0.f, 0.f, 0.f);
    if (node < NN) {
        int p = g_rowptr[node];
        const int end = g_rowptr[node + 1];
        const float dc = g_dinv[node];
        for (; p + 2 <= end; p += 2) {
            int r0 = g_erow[p];
            int r1 = g_erow[p + 1];
            float w0 = g_dinv[r0];
            float w1 = g_dinv[r1];
            float4 v0 = *((const float4*)(g_hw + (size_t)r0 * 128) + lane);
            float4 v1 = *((const float4*)(g_hw + (size_t)r1 * 128) + lane);
            acc.x += w0 * v0.x + w1 * v1.x;
            acc.y += w0 * v0.y + w1 * v1.y;
            acc.z += w0 * v0.z + w1 * v1.z;
            acc.w += w0 * v0.w + w1 * v1.w;
        }
        if (p < end) {
            int r0 = g_erow[p];
            float w0 = g_dinv[r0];
            float4 v0 = *((const float4*)(g_hw + (size_t)r0 * 128) + lane);
            acc.x += w0 * v0.x;
            acc.y += w0 * v0.y;
            acc.z += w0 * v0.z;
            acc.w += w0 * v0.w;
        }
        float4 b4 = *((const float4*)bias + lane);
        acc.x = fmaxf(fmaf(acc.x, dc, b4.x), 0.f);
        acc.y = fmaxf(fmaf(acc.y, dc, b4.y), 0.f);
        acc.z = fmaxf(fmaf(acc.z, dc, b4.z), 0.f);
        acc.w = fmaxf(fmaf(acc.w, dc, b4.w), 0.f);
        *((float4*)(g_agg + (size_t)node * 128) + lane) = acc;
    }

    __shared__ float ssum[8][128];
    __shared__ float ssq[8][128];
    int c0 = lane * 4;
    ssum[warp][c0 + 0] = acc.x;  ssq[warp][c0 + 0] = acc.x * acc.x;
    ssum[warp][c0 + 1] = acc.y;  ssq[warp][c0 + 1] = acc.y * acc.y;
    ssum[warp][c0 + 2] = acc.z;  ssq[warp][c0 + 2] = acc.z * acc.z;
    ssum[warp][c0 + 3] = acc.w;  ssq[warp][c0 + 3] = acc.w * acc.w;
    __syncthreads();
    int c = threadIdx.x & 127;
    bool issq = threadIdx.x >= 128;
    float t = 0.f;
#pragma unroll
    for (int i = 0; i < 8; i++) t += issq ? ssq[i][c] : ssum[i][c];
    atomicAdd(&g_stats[layer * 256 + (issq ? 128 : 0) + c], t);
}

// ---------------- BN params ----------------
__global__ void __launch_bounds__(128) bnparams_kernel(int layer,
                                                       const float* __restrict__ gamma,
                                                       const float* __restrict__ beta) {
    int c = threadIdx.x;
    const float invN = 1.0f / (float)NN;
    float mu = g_stats[layer * 256 + c] * invN;
    float var = g_stats[layer * 256 + 128 + c] * invN - mu * mu;
    float sc = rsqrtf(var + EPSV) * gamma[c];
    g_sc[layer * FF + c] = sc;
    g_sh[layer * FF + c] = beta[c] - mu * sc;
}

// ---------------- pooled raw sums ----------------
__global__ void __launch_bounds__(256) pooled_raw_kernel(int layer,
                                                         const int* __restrict__ batch) {
    int c = threadIdx.x & 127;
    int sub = threadIdx.x >> 7;
    int chunk = (NN + gridDim.x - 1) / gridDim.x;
    int r0 = blockIdx.x * chunk;
    int r1 = min(r0 + chunk, NN);

    int curg = -1;
    float acc = 0.f;
    for (int r = r0 + sub; r < r1; r += 2) {
        float v = g_agg[(size_t)r * 128 + c];
        int g = batch[r];
        if (g != curg) {
            if (curg >= 0)
                atomicAdd(&g_praw[(size_t)curg * (LL * FF) + layer * FF + c], acc);
            curg = g;
            acc = 0.f;
        }
        acc += v;
    }
    if (curg >= 0)
        atomicAdd(&g_praw[(size_t)curg * (LL * FF) + layer * FF + c], acc);
}

// ---------------- MLP head ----------------
__global__ void __launch_bounds__(128) mlp1_kernel(const float* __restrict__ W1,
                                                   const float* __restrict__ b1) {
    int g = blockIdx.x;
    int c = threadIdx.x;
    const float* p = g_praw + (size_t)g * (LL * FF);
    const float cnt = g_gcnt[g];
    float a0 = 0.f, a1 = 0.f, a2 = 0.f, a3 = 0.f;
#pragma unroll 4
    for (int k = 0; k < LL * FF; k += 4) {
        float v0 = fmaf(g_sc[k + 0], p[k + 0], cnt * g_sh[k + 0]);
        float v1 = fmaf(g_sc[k + 1], p[k + 1], cnt * g_sh[k + 1]);
        float v2 = fmaf(g_sc[k + 2], p[k + 2], cnt * g_sh[k + 2]);
        float v3 = fmaf(g_sc[k + 3], p[k + 3], cnt * g_sh[k + 3]);
        a0 = fmaf(v0, W1[(size_t)(k + 0) * FF + c], a0);
        a1 = fmaf(v1, W1[(size_t)(k + 1) * FF + c], a1);
        a2 = fmaf(v2, W1[(size_t)(k + 2) * FF + c], a2);
        a3 = fmaf(v3, W1[(size_t)(k + 3) * FF + c], a3);
    }
    g_z1[(size_t)g * FF + c] = (a0 + a1) + (a2 + a3) + b1[c];
}

__global__ void __launch_bounds__(128) bn2_stats_kernel() {
    int c = threadIdx.x;
    float s = 0.f, s2 = 0.f;
    for (int g = 0; g < GG; g++) {
        float v = g_z1[(size_t)g * FF + c];
        s += v;
        s2 = fmaf(v, v, s2);
    }
    g_stats2[c] = s;
    g_stats2[128 + c] = s2;
}

__global__ void __launch_bounds__(128) mlp2_kernel(const float* __restrict__ g1,
                                                   const float* __restrict__ bt1,
                                                   const float* __restrict__ W2,
                                                   const float* __restrict__ b2,
                                                   float* __restrict__ out) {
    int g = blockIdx.x;
    int c = threadIdx.x;
    __shared__ float y[FF];
    const float invG = 1.0f / (float)GG;
    float mu = g_stats2[c] * invG;
    float var = g_stats2[128 + c] * invG - mu * mu;
    float v = (g_z1[(size_t)g * FF + c] - mu) * rsqrtf(var + EPSV) * g1[c] + bt1[c];
    y[c] = fmaxf(v, 0.f);
    __syncthreads();
    if (c < OUTC) {
        float acc = b2[c];
#pragma unroll 8
        for (int k = 0; k < FF; k++)
            acc = fmaf(y[k], W2[(size_t)k * OUTC + c], acc);
        out[(size_t)g * OUTC + c] = acc;
    }
}

// ---------------- launch ----------------
extern "C" void kernel_launch(void* const* d_in, const int* in_sizes, int n_in,
                              void* d_out, int out_size) {
    const float* x = (const float*)d_in[0];
    const int* ei = (const int*)d_in[1];
    const int* batch = (const int*)d_in[2];
    const float* Ws = (const float*)d_in[3];
    const float* bs = (const float*)d_in[4];
    const float* gammas = (const float*)d_in[5];
    const float* betas = (const float*)d_in[6];
    const float* W1 = (const float*)d_in[7];
    const float* b1 = (const float*)d_in[8];
    const float* g1 = (const float*)d_in[9];
    const float* bt1 = (const float*)d_in[10];
    const float* W2 = (const float*)d_in[11];
    const float* b2 = (const float*)d_in[12];
    float* out = (float*)d_out;

    zero_setup_kernel<<<512, 256>>>();
    hist_kernel<<<2048, 256>>>(ei);
    gcnt_kernel<<<512, 256>>>(batch);
    scanA_kernel<<<SCAN_NB, SCAN_BS>>>();
    scanB_kernel<<<1, 256>>>();
    scanC_kernel<<<SCAN_NB, SCAN_BS>>>();
    place_kernel<<<2048, 256>>>(ei);

    const int gemm_blocks = (NN + 127) / 128;   // 782
    const int agg_blocks = (NN + 7) / 8;        // 12500

    for (int t = 0; t < LL; t++) {
        sgemm128_kernel<<<gemm_blocks, 256>>>(x, Ws + (size_t)t * FF * FF,
                                              t - 1 /* -1 for t=0 -> use x */, NN);
        aggregate_kernel<<<agg_blocks, 256>>>(t, bs + (size_t)t * FF);
        bnparams_kernel<<<1, 128>>>(t, gammas + (size_t)t * FF, betas + (size_t)t * FF);
        pooled_raw_kernel<<<1024, 256>>>(t, batch);
    }

    mlp1_kernel<<<GG, 128>>>(W1, b1);
    bn2_stats_kernel<<<1, 128>>>();
    mlp2_kernel<<<GG, 128>>>(g1, bt1, W2, b2, out);
}

// round 17
// speedup vs baseline: 1.2654x; 1.0004x over previous
#include <cuda_runtime.h>
#include <cstdint>
#include <cstddef>

// Problem constants
#define NN 100000
#define EE 1600000
#define FF 128
#define LL 4
#define GG 512
#define OUTC 10
#define EPSV 1e-5f

#define SCAN_BS 512
#define SCAN_NB ((NN + SCAN_BS - 1) / SCAN_BS)   // 196

// ---------------- device scratch (static, no runtime allocation) ----------------
__device__ float g_hw[(size_t)NN * FF];    // h @ W
__device__ float g_agg[(size_t)NN * FF];   // relu(aggregate + bias), pre-affine
__device__ float g_dinv[NN];
__device__ int   g_cnt[NN];                // per-node in-degree (histogram)
__device__ int   g_rowptr[NN + 1];         // CSR offsets (by destination col)
__device__ int   g_off[NN];                // placement cursors
__device__ int   g_erow[EE];               // CSR-ordered source (row) ids
__device__ int   g_bsum[SCAN_NB];          // per-block count sums
__device__ int   g_boff[SCAN_NB];          // exclusive block offsets
__device__ float g_stats[LL * 2 * FF];     // per-layer per-channel sum, sumsq
__device__ float g_sc[LL * FF];            // BN scale per layer
__device__ float g_sh[LL * FF];            // BN shift per layer
__device__ float g_praw[(size_t)GG * LL * FF]; // per-graph sums of raw relu values
__device__ float g_gcnt[GG];               // nodes per graph
__device__ float g_z1[(size_t)GG * FF];
__device__ float g_stats2[2 * FF];

// ---------------- setup kernels ----------------
__global__ void zero_setup_kernel() {
    size_t i = (size_t)blockIdx.x * blockDim.x + threadIdx.x;
    size_t stride = (size_t)gridDim.x * blockDim.x;
    for (size_t j = i; j < (size_t)GG * LL * FF; j += stride) g_praw[j] = 0.f;
    for (size_t j = i; j < NN; j += stride) g_cnt[j] = 0;
    for (size_t j = i; j < LL * 2 * FF; j += stride) g_stats[j] = 0.f;
    for (size_t j = i; j < GG; j += stride) g_gcnt[j] = 0.f;
}

__global__ void hist_kernel(const int* __restrict__ ei) {
    size_t i = (size_t)blockIdx.x * blockDim.x + threadIdx.x;
    size_t stride = (size_t)gridDim.x * blockDim.x;
    for (size_t e = i; e < EE; e += stride)
        atomicAdd(&g_cnt[ei[EE + e]], 1);
}

__global__ void gcnt_kernel(const int* __restrict__ batch) {
    size_t i = (size_t)blockIdx.x * blockDim.x + threadIdx.x;
    size_t stride = (size_t)gridDim.x * blockDim.x;
    for (size_t j = i; j < NN; j += stride)
        atomicAdd(&g_gcnt[batch[j]], 1.0f);
}

// ---------------- parallel 3-phase scan of g_cnt ----------------
// Phase A: per-block sum of 512 counts
__global__ void __launch_bounds__(SCAN_BS) scanA_kernel() {
    __shared__ int sh[SCAN_BS];
    int t = threadIdx.x;
    int idx = blockIdx.x * SCAN_BS + t;
    sh[t] = (idx < NN) ? g_cnt[idx] : 0;
    __syncthreads();
#pragma unroll
    for (int d = SCAN_BS / 2; d > 0; d >>= 1) {
        if (t < d) sh[t] += sh[t + d];
        __syncthreads();
    }
    if (t == 0) g_bsum[blockIdx.x] = sh[0];
}

// Phase B: exclusive scan of the 196 block sums (one block)
__global__ void __launch_bounds__(256) scanB_kernel() {
    __shared__ int sh[256];
    int t = threadIdx.x;
    sh[t] = (t < SCAN_NB) ? g_bsum[t] : 0;
    __syncthreads();
    for (int d = 1; d < 256; d <<= 1) {
        int v = (t >= d) ? sh[t - d] : 0;
        __syncthreads();
        sh[t] += v;
        __syncthreads();
    }
    if (t < SCAN_NB) g_boff[t] = (t == 0) ? 0 : sh[t - 1];
}

// Phase C: per-block exclusive scan + block offset -> rowptr/off/dinv
__global__ void __launch_bounds__(SCAN_BS) scanC_kernel() {
    __shared__ int sh[SCAN_BS];
    int t = threadIdx.x;
    int idx = blockIdx.x * SCAN_BS + t;
    int c = (idx < NN) ? g_cnt[idx] : 0;
    sh[t] = c;
    __syncthreads();
    // Hillis-Steele inclusive scan over 512
    for (int d = 1; d < SCAN_BS; d <<= 1) {
        int v = (t >= d) ? sh[t - d] : 0;
        __syncthreads();
        sh[t] += v;
        __syncthreads();
    }
    if (idx < NN) {
        int excl = sh[t] - c + g_boff[blockIdx.x];
        g_rowptr[idx] = excl;
        g_off[idx] = excl;
        g_dinv[idx] = c > 0 ? rsqrtf((float)c) : 0.f;
    }
    if (idx == 0) g_rowptr[NN] = EE;  // all edge dests are in [0, NN)
}

__global__ void place_kernel(const int* __restrict__ ei) {
    size_t i = (size_t)blockIdx.x * blockDim.x + threadIdx.x;
    size_t stride = (size_t)gridDim.x * blockDim.x;
    for (size_t e = i; e < EE; e += stride) {
        int r = ei[e];
        int c = ei[EE + e];
        int pos = atomicAdd(&g_off[c], 1);
        g_erow[pos] = r;
    }
}

// ---------------- SGEMM: C[M,128] = affine(A)[M,128] @ W[128,128] ------------
// layer_affine < 0: A = x (external), no affine.
// layer_affine >= 0: A = g_agg, element (row,k) -> a*g_sc[la*128+k]+g_sh[la*128+k]
__global__ void __launch_bounds__(256) sgemm128_kernel(const float* __restrict__ x,
                                                       const float* __restrict__ W,
                                                       int layer_affine,
                                                       int M) {
    __shared__ float As[8][128];
    __shared__ float Bs[8][128];
    const float* __restrict__ A = (layer_affine < 0) ? x : g_agg;
    float* __restrict__ C = g_hw;

    const int tid = threadIdx.x;
    const int m0 = blockIdx.x * 128;
    const int tr = (tid >> 4) << 3;
    const int tc = (tid & 15) << 3;

    const int a_row = tid >> 1;
    const int a_col = (tid & 1) << 2;
    const int b_row = tid >> 5;
    const int b_col = (tid & 31) << 2;

    float acc[8][8];
#pragma unroll
    for (int i = 0; i < 8; i++)
#pragma unroll
        for (int j = 0; j < 8; j++) acc[i][j] = 0.f;

    for (int k0 = 0; k0 < 128; k0 += 8) {
        float4 av = make_float4(0.f, 0.f, 0.f, 0.f);
        int gr = m0 + a_row;
        if (gr < M) {
            av = *(const float4*)(A + (size_t)gr * 128 + k0 + a_col);
            if (layer_affine >= 0) {
                const float* scp = g_sc + layer_affine * FF + k0 + a_col;
                const float* shp = g_sh + layer_affine * FF + k0 + a_col;
                float4 s4 = *(const float4*)scp;
                float4 h4 = *(const float4*)shp;
                av.x = fmaf(av.x, s4.x, h4.x);
                av.y = fmaf(av.y, s4.y, h4.y);
                av.z = fmaf(av.z, s4.z, h4.z);
                av.w = fmaf(av.w, s4.w, h4.w);
            }
        }
        As[a_col + 0][a_row] = av.x;
        As[a_col + 1][a_row] = av.y;
        As[a_col + 2][a_row] = av.z;
        As[a_col + 3][a_row] = av.w;
        float4 bv = *(const float4*)(W + (size_t)(k0 + b_row) * 128 + b_col);
        *(float4*)&Bs[b_row][b_col] = bv;
        __syncthreads();
#pragma unroll
        for (int k = 0; k < 8; k++) {
            float ra[8], rb[8];
            *(float4*)&ra[0] = *(const float4*)&As[k][tr];
            *(float4*)&ra[4] = *(const float4*)&As[k][tr + 4];
            *(float4*)&rb[0] = *(const float4*)&Bs[k][tc];
            *(float4*)&rb[4] = *(const float4*)&Bs[k][tc + 4];
#pragma unroll
            for (int i = 0; i < 8; i++)
#pragma unroll
                for (int j = 0; j < 8; j++)
                    acc[i][j] = fmaf(ra[i], rb[j], acc[i][j]);
        }
        __syncthreads();
    }
#pragma unroll
    for (int i = 0; i < 8; i++) {
        int gr = m0 + tr + i;
        if (gr < M) {
            *(float4*)(C + (size_t)gr * 128 + tc) =
                make_float4(acc[i][0], acc[i][1], acc[i][2], acc[i][3]);
            *(float4*)(C + (size_t)gr * 128 + tc + 4) =
                make_float4(acc[i][4], acc[i][5], acc[i][6], acc[i][7]);
        }
    }
}

// ---------------- fused aggregation: CSR gather + bias + relu + BN stats ----
__global__ void __launch_bounds__(256) aggregate_kernel(int layer,
                                                        const float* __restrict__ bias) {
    const int warp = threadIdx.x >> 5;
    const int lane = threadIdx.x & 31;
    const int node = blockIdx.x * 8 + warp;

    float4 acc = make_float4(0.f, 0.f, 0.f, 0.f);
    if (node < NN) {
        int p = g_rowptr[node];
        const int end = g_rowptr[node + 1];
        const float dc = g_dinv[node];
        for (; p + 2 <= end; p += 2) {
            int r0 = g_erow[p];
            int r1 = g_erow[p + 1];
            float w0 = g_dinv[r0];
            float w1 = g_dinv[r1];
            float4 v0 = *((const float4*)(g_hw + (size_t)r0 * 128) + lane);
            float4 v1 = *((const float4*)(g_hw + (size_t)r1 * 128) + lane);
            acc.x += w0 * v0.x + w1 * v1.x;
            acc.y += w0 * v0.y + w1 * v1.y;
            acc.z += w0 * v0.z + w1 * v1.z;
            acc.w += w0 * v0.w + w1 * v1.w;
        }
        if (p < end) {
            int r0 = g_erow[p];
            float w0 = g_dinv[r0];
            float4 v0 = *((const float4*)(g_hw + (size_t)r0 * 128) + lane);
            acc.x += w0 * v0.x;
            acc.y += w0 * v0.y;
            acc.z += w0 * v0.z;
            acc.w += w0 * v0.w;
        }
        float4 b4 = *((const float4*)bias + lane);
        acc.x = fmaxf(fmaf(acc.x, dc, b4.x), 0.f);
        acc.y = fmaxf(fmaf(acc.y, dc, b4.y), 0.f);
        acc.z = fmaxf(fmaf(acc.z, dc, b4.z), 0.f);
        acc.w = fmaxf(fmaf(acc.w, dc, b4.w), 0.f);
        *((float4*)(g_agg + (size_t)node * 128) + lane) = acc;
    }

    __shared__ float ssum[8][128];
    __shared__ float ssq[8][128];
    int c0 = lane * 4;
    ssum[warp][c0 + 0] = acc.x;  ssq[warp][c0 + 0] = acc.x * acc.x;
    ssum[warp][c0 + 1] = acc.y;  ssq[warp][c0 + 1] = acc.y * acc.y;
    ssum[warp][c0 + 2] = acc.z;  ssq[warp][c0 + 2] = acc.z * acc.z;
    ssum[warp][c0 + 3] = acc.w;  ssq[warp][c0 + 3] = acc.w * acc.w;
    __syncthreads();
    int c = threadIdx.x & 127;
    bool issq = threadIdx.x >= 128;
    float t = 0.f;
#pragma unroll
    for (int i = 0; i < 8; i++) t += issq ? ssq[i][c] : ssum[i][c];
    atomicAdd(&g_stats[layer * 256 + (issq ? 128 : 0) + c], t);
}

// ---------------- BN params ----------------
__global__ void __launch_bounds__(128) bnparams_kernel(int layer,
                                                       const float* __restrict__ gamma,
                                                       const float* __restrict__ beta) {
    int c = threadIdx.x;
    const float invN = 1.0f / (float)NN;
    float mu = g_stats[layer * 256 + c] * invN;
    float var = g_stats[layer * 256 + 128 + c] * invN - mu * mu;
    float sc = rsqrtf(var + EPSV) * gamma[c];
    g_sc[layer * FF + c] = sc;
    g_sh[layer * FF + c] = beta[c] - mu * sc;
}

// ---------------- pooled raw sums ----------------
__global__ void __launch_bounds__(256) pooled_raw_kernel(int layer,
                                                         const int* __restrict__ batch) {
    int c = threadIdx.x & 127;
    int sub = threadIdx.x >> 7;
    int chunk = (NN + gridDim.x - 1) / gridDim.x;
    int r0 = blockIdx.x * chunk;
    int r1 = min(r0 + chunk, NN);

    int curg = -1;
    float acc = 0.f;
    for (int r = r0 + sub; r < r1; r += 2) {
        float v = g_agg[(size_t)r * 128 + c];
        int g = batch[r];
        if (g != curg) {
            if (curg >= 0)
                atomicAdd(&g_praw[(size_t)curg * (LL * FF) + layer * FF + c], acc);
            curg = g;
            acc = 0.f;
        }
        acc += v;
    }
    if (curg >= 0)
        atomicAdd(&g_praw[(size_t)curg * (LL * FF) + layer * FF + c], acc);
}

// ---------------- MLP head ----------------
__global__ void __launch_bounds__(128) mlp1_kernel(const float* __restrict__ W1,
                                                   const float* __restrict__ b1) {
    int g = blockIdx.x;
    int c = threadIdx.x;
    const float* p = g_praw + (size_t)g * (LL * FF);
    const float cnt = g_gcnt[g];
    float a0 = 0.f, a1 = 0.f, a2 = 0.f, a3 = 0.f;
#pragma unroll 4
    for (int k = 0; k < LL * FF; k += 4) {
        float v0 = fmaf(g_sc[k + 0], p[k + 0], cnt * g_sh[k + 0]);
        float v1 = fmaf(g_sc[k + 1], p[k + 1], cnt * g_sh[k + 1]);
        float v2 = fmaf(g_sc[k + 2], p[k + 2], cnt * g_sh[k + 2]);
        float v3 = fmaf(g_sc[k + 3], p[k + 3], cnt * g_sh[k + 3]);
        a0 = fmaf(v0, W1[(size_t)(k + 0) * FF + c], a0);
        a1 = fmaf(v1, W1[(size_t)(k + 1) * FF + c], a1);
        a2 = fmaf(v2, W1[(size_t)(k + 2) * FF + c], a2);
        a3 = fmaf(v3, W1[(size_t)(k + 3) * FF + c], a3);
    }
    g_z1[(size_t)g * FF + c] = (a0 + a1) + (a2 + a3) + b1[c];
}

__global__ void __launch_bounds__(128) bn2_stats_kernel() {
    int c = threadIdx.x;
    float s = 0.f, s2 = 0.f;
    for (int g = 0; g < GG; g++) {
        float v = g_z1[(size_t)g * FF + c];
        s += v;
        s2 = fmaf(v, v, s2);
    }
    g_stats2[c] = s;
    g_stats2[128 + c] = s2;
}

__global__ void __launch_bounds__(128) mlp2_kernel(const float* __restrict__ g1,
                                                   const float* __restrict__ bt1,
                                                   const float* __restrict__ W2,
                                                   const float* __restrict__ b2,
                                                   float* __restrict__ out) {
    int g = blockIdx.x;
    int c = threadIdx.x;
    __shared__ float y[FF];
    const float invG = 1.0f / (float)GG;
    float mu = g_stats2[c] * invG;
    float var = g_stats2[128 + c] * invG - mu * mu;
    float v = (g_z1[(size_t)g * FF + c] - mu) * rsqrtf(var + EPSV) * g1[c] + bt1[c];
    y[c] = fmaxf(v, 0.f);
    __syncthreads();
    if (c < OUTC) {
        float acc = b2[c];
#pragma unroll 8
        for (int k = 0; k < FF; k++)
            acc = fmaf(y[k], W2[(size_t)k * OUTC + c], acc);
        out[(size_t)g * OUTC + c] = acc;
    }
}

// ---------------- launch ----------------
extern "C" void kernel_launch(void* const* d_in, const int* in_sizes, int n_in,
                              void* d_out, int out_size) {
    const float* x = (const float*)d_in[0];
    const int* ei = (const int*)d_in[1];
    const int* batch = (const int*)d_in[2];
    const float* Ws = (const float*)d_in[3];
    const float* bs = (const float*)d_in[4];
    const float* gammas = (const float*)d_in[5];
    const float* betas = (const float*)d_in[6];
    const float* W1 = (const float*)d_in[7];
    const float* b1 = (const float*)d_in[8];
    const float* g1 = (const float*)d_in[9];
    const float* bt1 = (const float*)d_in[10];
    const float* W2 = (const float*)d_in[11];
    const float* b2 = (const float*)d_in[12];
    float* out = (float*)d_out;

    zero_setup_kernel<<<512, 256>>>();
    hist_kernel<<<2048, 256>>>(ei);
    gcnt_kernel<<<512, 256>>>(batch);
    scanA_kernel<<<SCAN_NB, SCAN_BS>>>();
    scanB_kernel<<<1, 256>>>();
    scanC_kernel<<<SCAN_NB, SCAN_BS>>>();
    place_kernel<<<2048, 256>>>(ei);

    const int gemm_blocks = (NN + 127) / 128;   // 782
    const int agg_blocks = (NN + 7) / 8;        // 12500

    for (int t = 0; t < LL; t++) {
        sgemm128_kernel<<<gemm_blocks, 256>>>(x, Ws + (size_t)t * FF * FF,
                                              t - 1 /* -1 for t=0 -> use x */, NN);
        aggregate_kernel<<<agg_blocks, 256>>>(t, bs + (size_t)t * FF);
        bnparams_kernel<<<1, 128>>>(t, gammas + (size_t)t * FF, betas + (size_t)t * FF);
        pooled_raw_kernel<<<1024, 256>>>(t, batch);
    }

    mlp1_kernel<<<GG, 128>>>(W1, b1);
    bn2_stats_kernel<<<1, 128>>>();
    mlp2_kernel<<<GG, 128>>>(g1, bt1, W2, b2, out);
}